// round 1
// baseline (speedup 1.0000x reference)
#include <cuda_runtime.h>
#include <cstdint>

// Problem shape (fixed by the dataset)
#define B  64
#define C  64
#define NQ 32
#define S  1024
#define D  128
#define TS 128          // doc tokens per smem tile
#define TEMP_INV 50.0f  // 1 / 0.02

// Scratch for the 64x64 score matrix (allocation-free per harness rules)
__device__ float g_scores[B * C];

// ---------------------------------------------------------------------------
// Kernel 1: one block per (b, c) pair.
//   scores[b][c] = sum_n max_s dot(q[b][n][:], d[c][s][:])
//
// smem layout:
//   qsh[n][k]  : 32 x 128 fp32, linear (16 KB). Compute reads are warp-uniform
//                (broadcast), so no transpose / padding needed.
//   dsh[k][s'] : 128 x 128 fp32 (64 KB), transposed with XOR swizzle
//                s' = s ^ (k >> 2).
//                STS (transpose): lanes vary kq=k>>2 at fixed s -> banks s^kq
//                all distinct -> conflict-free.
//                LDS (compute): fixed k, lanes vary s stride-1 -> banks
//                (s^(k>>2)) distinct -> conflict-free.
//
// Thread micro-tile: 4n x 4s.  tn = warp id (0..7), ts = lane (0..31).
//   n_i = tn + 8*i   (i=0..3)  -> q reads broadcast within the warp
//   s_j = ts + 32*j  (j=0..3)  -> d reads stride-1 within the warp
// ---------------------------------------------------------------------------
__global__ __launch_bounds__(256, 2)
void colbert_scores_kernel(const float* __restrict__ q,
                           const float* __restrict__ d)
{
    extern __shared__ float sh[];
    float* qsh = sh;                 // NQ * D      = 4096 floats
    float* dsh = sh + NQ * D;        // D  * TS     = 16384 floats
    // total smem = (4096 + 16384) * 4 = 81920 bytes

    const int b   = blockIdx.y;
    const int c   = blockIdx.x;
    const int tid = threadIdx.x;
    const int tn  = tid >> 5;        // warp id 0..7
    const int ts  = tid & 31;        // lane

    const float* __restrict__ qb = q + (size_t)b * NQ * D;
    const float* __restrict__ dc = d + (size_t)c * S  * D;

    // ---- load q tile (linear copy, fully coalesced, conflict-free STS) ----
    // 4096 floats = 1024 float4 -> 4 per thread
    #pragma unroll
    for (int i = 0; i < 4; i++) {
        int idx = tid + i * 256;                 // float4 index 0..1023
        reinterpret_cast<float4*>(qsh)[idx] =
            reinterpret_cast<const float4*>(qb)[idx];
    }

    float runmax[4];
    #pragma unroll
    for (int i = 0; i < 4; i++) runmax[i] = __int_as_float(0xff800000); // -inf

    for (int st = 0; st < S; st += TS) {
        __syncthreads();   // protect dsh from previous iteration's readers

        // ---- load + transpose d tile: 16384 floats = 4096 float4 ----
        // idx -> kq = idx & 31 (float4 along k), s = idx >> 5 (0..127)
        // global: lanes of a warp share s, consecutive kq -> 512B coalesced
        #pragma unroll
        for (int i = 0; i < 16; i++) {
            int idx = tid + i * 256;
            int kq  = idx & 31;
            int s   = idx >> 5;
            float4 v = reinterpret_cast<const float4*>(dc + (size_t)(st + s) * D)[kq];
            int scol = s ^ kq;                   // swizzled column (k>>2 == kq)
            dsh[(4 * kq + 0) * TS + scol] = v.x;
            dsh[(4 * kq + 1) * TS + scol] = v.y;
            dsh[(4 * kq + 2) * TS + scol] = v.z;
            dsh[(4 * kq + 3) * TS + scol] = v.w;
        }
        __syncthreads();

        // ---- 32x128 GEMM tile, micro 4x4 ----
        float acc[4][4];
        #pragma unroll
        for (int i = 0; i < 4; i++)
            #pragma unroll
            for (int j = 0; j < 4; j++) acc[i][j] = 0.0f;

        #pragma unroll 8
        for (int k = 0; k < D; k++) {
            const int txs = ts ^ (k >> 2);       // swizzled lane column
            float qv[4], dv[4];
            #pragma unroll
            for (int i = 0; i < 4; i++)
                qv[i] = qsh[(tn + 8 * i) * D + k];       // broadcast
            #pragma unroll
            for (int j = 0; j < 4; j++)
                dv[j] = dsh[k * TS + 32 * j + txs];      // conflict-free
            #pragma unroll
            for (int i = 0; i < 4; i++)
                #pragma unroll
                for (int j = 0; j < 4; j++)
                    acc[i][j] = fmaf(qv[i], dv[j], acc[i][j]);
        }

        // fold this tile's 4 s-columns into the running max per n
        #pragma unroll
        for (int i = 0; i < 4; i++) {
            float m = fmaxf(fmaxf(acc[i][0], acc[i][1]),
                            fmaxf(acc[i][2], acc[i][3]));
            runmax[i] = fmaxf(runmax[i], m);
        }
    }

    // ---- reduce: max over lanes (s partitions), then sum over n ----
    #pragma unroll
    for (int i = 0; i < 4; i++) {
        float m = runmax[i];
        #pragma unroll
        for (int off = 16; off > 0; off >>= 1)
            m = fmaxf(m, __shfl_xor_sync(0xffffffffu, m, off));
        runmax[i] = m;
    }

    __shared__ float warp_sum[8];
    if (ts == 0)
        warp_sum[tn] = runmax[0] + runmax[1] + runmax[2] + runmax[3];
    __syncthreads();

    if (tid == 0) {
        float ssum = 0.0f;
        #pragma unroll
        for (int w = 0; w < 8; w++) ssum += warp_sum[w];
        g_scores[b * C + c] = ssum;
    }
}

// ---------------------------------------------------------------------------
// Kernel 2: normalize, log-softmax per row, NLL mean. 1 block, 64 threads.
// ---------------------------------------------------------------------------
__global__ void colbert_loss_kernel(const float* __restrict__ q,
                                    const int*   __restrict__ offset_p,
                                    float*       __restrict__ out)
{
    __shared__ float losses[B];
    const int b = threadIdx.x;

    if (b < B) {
        // lengths[b] = count of q[b, n, 0] != 0
        int len = 0;
        #pragma unroll
        for (int n = 0; n < NQ; n++)
            len += (q[(size_t)b * NQ * D + (size_t)n * D] != 0.0f) ? 1 : 0;

        const float inv = TEMP_INV / (float)len;   // (1/len) * (1/T)
        const float* row = g_scores + b * C;

        float logits[C];
        float mx = __int_as_float(0xff800000);
        #pragma unroll
        for (int cc = 0; cc < C; cc++) {
            float l = row[cc] * inv;
            logits[cc] = l;
            mx = fmaxf(mx, l);
        }
        float se = 0.0f;
        #pragma unroll
        for (int cc = 0; cc < C; cc++)
            se += expf(logits[cc] - mx);

        const int label = b + offset_p[0];
        const float lp  = logits[label] - mx - logf(se);
        losses[b] = -lp;
    }
    __syncthreads();

    if (b == 0) {
        float ssum = 0.0f;
        #pragma unroll
        for (int i = 0; i < B; i++) ssum += losses[i];
        out[0] = ssum / (float)B;
    }
}

// ---------------------------------------------------------------------------
extern "C" void kernel_launch(void* const* d_in, const int* in_sizes, int n_in,
                              void* d_out, int out_size)
{
    const float* q   = (const float*)d_in[0];
    const float* d   = (const float*)d_in[1];
    const int*   off = (const int*)  d_in[2];
    float*       out = (float*)d_out;

    const size_t smem_bytes = (size_t)(NQ * D + D * TS) * sizeof(float); // 81920

    // Opt in to >48KB dynamic smem. Not a stream op: executes at capture time,
    // idempotent, no allocation.
    cudaFuncSetAttribute(colbert_scores_kernel,
                         cudaFuncAttributeMaxDynamicSharedMemorySize,
                         (int)smem_bytes);

    dim3 grid(C, B);
    colbert_scores_kernel<<<grid, 256, smem_bytes>>>(q, d);
    colbert_loss_kernel<<<1, 64>>>(q, off, out);
}

// round 2
// speedup vs baseline: 5.2400x; 5.2400x over previous
#include <cuda_runtime.h>
#include <cstdint>

// Problem shape (fixed)
#define B   64
#define C   64
#define NQ  32
#define S   1024
#define KD  128          // embedding dim
#define MT  128          // rows per block (4 b's * 32 n)
#define NT  128          // doc tokens per s-tile
#define PAD 132          // smem row stride (floats): (4r+c)%32 distinct -> conflict-free
#define TEMP_INV 50.0f

__device__ float g_scores[B * C];

__device__ __forceinline__ uint32_t s2u(const void* p) {
    return (uint32_t)__cvta_generic_to_shared(p);
}
__device__ __forceinline__ void cp_async16(float* dst, const float* src) {
    asm volatile("cp.async.cg.shared.global [%0], [%1], 16;\n"
                 :: "r"(s2u(dst)), "l"(src));
}

// ---------------------------------------------------------------------------
// Kernel 1: tf32 mma.sync GEMM with fused max/sum epilogue.
// Block (mtile, c): rows = Q_all[mtile*128 .. +128)  (Q_all is [B*NQ, 128]),
// loops over all 8 s-tiles of d_c, keeps per-row running max, then reduces.
// 8 warps, warp grid 4(M) x 2(N): warp tile 32x64, micro m16n8k8 tf32.
// ---------------------------------------------------------------------------
__global__ __launch_bounds__(256)
void colbert_scores_mma(const float* __restrict__ q,
                        const float* __restrict__ d)
{
    extern __shared__ float sh[];
    float* qs = sh;                    // MT * PAD
    float* ds = sh + MT * PAD;         // 2 * NT * PAD (double buffer)

    const int mtile = blockIdx.x;      // 0..15
    const int c     = blockIdx.y;      // 0..63
    const int tid   = threadIdx.x;
    const int wid   = tid >> 5;
    const int lane  = tid & 31;
    const int warp_m = wid >> 1;       // 0..3
    const int warp_n = wid & 1;        // 0..1
    const int gID   = lane >> 2;       // groupID
    const int tig   = lane & 3;        // threadID_in_group

    const float* __restrict__ qbase = q + (size_t)mtile * MT * KD;
    const float* __restrict__ dbase = d + (size_t)c * S * KD;

    // ---- load Q tile (once), padded smem ----
    #pragma unroll
    for (int i = 0; i < 16; i++) {
        int idx  = i * 256 + tid;          // float4 index 0..4095
        int row  = idx >> 5;
        int c4   = idx & 31;
        float4 v = reinterpret_cast<const float4*>(qbase)[idx];
        *reinterpret_cast<float4*>(&qs[row * PAD + c4 * 4]) = v;
    }

    // ---- prefetch D s-tile 0 ----
    #pragma unroll
    for (int i = 0; i < 16; i++) {
        int idx = i * 256 + tid;
        int row = idx >> 5;
        int c4  = idx & 31;
        cp_async16(&ds[row * PAD + c4 * 4], dbase + (size_t)row * KD + c4 * 4);
    }
    asm volatile("cp.async.commit_group;\n");

    float runmax[2][2];
    #pragma unroll
    for (int mt = 0; mt < 2; mt++)
        #pragma unroll
        for (int h = 0; h < 2; h++)
            runmax[mt][h] = __int_as_float(0xff800000);

    __syncthreads();   // qs visible to all before compute

    for (int t = 0; t < S / NT; t++) {
        // prefetch next tile into other buffer
        if (t < S / NT - 1) {
            float* dst = ds + ((t + 1) & 1) * NT * PAD;
            const float* src = dbase + (size_t)(t + 1) * NT * KD;
            #pragma unroll
            for (int i = 0; i < 16; i++) {
                int idx = i * 256 + tid;
                int row = idx >> 5;
                int c4  = idx & 31;
                cp_async16(&dst[row * PAD + c4 * 4], src + (size_t)row * KD + c4 * 4);
            }
            asm volatile("cp.async.commit_group;\n");
            asm volatile("cp.async.wait_group 1;\n");
        } else {
            asm volatile("cp.async.wait_group 0;\n");
        }
        __syncthreads();   // current tile visible; prev compute done (trailing sync)

        const float* db = ds + (t & 1) * NT * PAD;

        float acc[2][8][4];
        #pragma unroll
        for (int mt = 0; mt < 2; mt++)
            #pragma unroll
            for (int nt = 0; nt < 8; nt++)
                #pragma unroll
                for (int r = 0; r < 4; r++) acc[mt][nt][r] = 0.0f;

        const int arow = warp_m * 32 + gID;
        const int brow = warp_n * 64 + gID;

        #pragma unroll
        for (int ks = 0; ks < 16; ks++) {
            const int k0 = ks * 8;
            uint32_t a[2][4];
            #pragma unroll
            for (int mt = 0; mt < 2; mt++) {
                const float* ap = &qs[(arow + mt * 16) * PAD + k0 + tig];
                a[mt][0] = __float_as_uint(ap[0]);
                a[mt][1] = __float_as_uint(ap[8 * PAD]);
                a[mt][2] = __float_as_uint(ap[4]);
                a[mt][3] = __float_as_uint(ap[8 * PAD + 4]);
            }
            uint32_t bf[8][2];
            #pragma unroll
            for (int nt = 0; nt < 8; nt++) {
                const float* bp = &db[(brow + nt * 8) * PAD + k0 + tig];
                bf[nt][0] = __float_as_uint(bp[0]);
                bf[nt][1] = __float_as_uint(bp[4]);
            }
            #pragma unroll
            for (int mt = 0; mt < 2; mt++)
                #pragma unroll
                for (int nt = 0; nt < 8; nt++) {
                    asm volatile(
                        "mma.sync.aligned.m16n8k8.row.col.f32.tf32.tf32.f32 "
                        "{%0,%1,%2,%3}, {%4,%5,%6,%7}, {%8,%9}, {%0,%1,%2,%3};\n"
                        : "+f"(acc[mt][nt][0]), "+f"(acc[mt][nt][1]),
                          "+f"(acc[mt][nt][2]), "+f"(acc[mt][nt][3])
                        : "r"(a[mt][0]), "r"(a[mt][1]), "r"(a[mt][2]), "r"(a[mt][3]),
                          "r"(bf[nt][0]), "r"(bf[nt][1]));
                }
        }

        // fold this s-tile into running max.
        // c0,c1 -> row gID (h=0); c2,c3 -> row gID+8 (h=1). Cols irrelevant (max over all s).
        #pragma unroll
        for (int mt = 0; mt < 2; mt++) {
            float m0 = __int_as_float(0xff800000);
            float m1 = __int_as_float(0xff800000);
            #pragma unroll
            for (int nt = 0; nt < 8; nt++) {
                m0 = fmaxf(m0, fmaxf(acc[mt][nt][0], acc[mt][nt][1]));
                m1 = fmaxf(m1, fmaxf(acc[mt][nt][2], acc[mt][nt][3]));
            }
            runmax[mt][0] = fmaxf(runmax[mt][0], m0);
            runmax[mt][1] = fmaxf(runmax[mt][1], m1);
        }
        __syncthreads();   // all reads of this buffer done before next prefetch overwrites
    }

    // ---- reduce: quad max (lanes sharing a row), publish per (warp_n, row) ----
    // reuse qs as redbuf[2][128]
    float* red = qs;
    #pragma unroll
    for (int mt = 0; mt < 2; mt++)
        #pragma unroll
        for (int h = 0; h < 2; h++) {
            float m = runmax[mt][h];
            m = fmaxf(m, __shfl_xor_sync(0xffffffffu, m, 1));
            m = fmaxf(m, __shfl_xor_sync(0xffffffffu, m, 2));
            if (tig == 0) {
                int row = warp_m * 32 + mt * 16 + h * 8 + gID;
                red[warp_n * 128 + row] = m;
            }
        }
    __syncthreads();

    // rows wid*32..+31 belong to b_global = mtile*4 + wid; n = lane
    if (wid < 4) {
        int row = wid * 32 + lane;
        float v = fmaxf(red[row], red[128 + row]);
        #pragma unroll
        for (int off = 16; off > 0; off >>= 1)
            v += __shfl_xor_sync(0xffffffffu, v, off);
        if (lane == 0)
            g_scores[(mtile * 4 + wid) * C + c] = v;
    }
}

// ---------------------------------------------------------------------------
// Kernel 2: normalize, log-softmax, NLL mean. 1 block, 64 threads.
// ---------------------------------------------------------------------------
__global__ void colbert_loss_kernel(const float* __restrict__ q,
                                    const int*   __restrict__ offset_p,
                                    float*       __restrict__ out)
{
    __shared__ float losses[B];
    const int b = threadIdx.x;

    if (b < B) {
        int len = 0;
        #pragma unroll
        for (int n = 0; n < NQ; n++)
            len += (q[(size_t)b * NQ * KD + (size_t)n * KD] != 0.0f) ? 1 : 0;

        const float inv = TEMP_INV / (float)len;
        const float* row = g_scores + b * C;

        float logits[C];
        float mx = __int_as_float(0xff800000);
        #pragma unroll
        for (int cc = 0; cc < C; cc++) {
            float l = row[cc] * inv;
            logits[cc] = l;
            mx = fmaxf(mx, l);
        }
        float se = 0.0f;
        #pragma unroll
        for (int cc = 0; cc < C; cc++)
            se += expf(logits[cc] - mx);

        const int label = b + offset_p[0];
        losses[b] = -(logits[label] - mx - logf(se));
    }
    __syncthreads();

    if (b == 0) {
        float ssum = 0.0f;
        #pragma unroll
        for (int i = 0; i < B; i++) ssum += losses[i];
        out[0] = ssum / (float)B;
    }
}

// ---------------------------------------------------------------------------
extern "C" void kernel_launch(void* const* d_in, const int* in_sizes, int n_in,
                              void* d_out, int out_size)
{
    const float* q   = (const float*)d_in[0];
    const float* d   = (const float*)d_in[1];
    const int*   off = (const int*)  d_in[2];
    float*       out = (float*)d_out;

    const size_t smem_bytes = (size_t)(MT * PAD + 2 * NT * PAD) * sizeof(float); // 202752

    cudaFuncSetAttribute(colbert_scores_mma,
                         cudaFuncAttributeMaxDynamicSharedMemorySize,
                         (int)smem_bytes);

    dim3 grid(16, C);   // x = mtile (same-c blocks adjacent -> L2 reuse of d_c)
    colbert_scores_mma<<<grid, 256, smem_bytes>>>(q, d);
    colbert_loss_kernel<<<1, 64>>>(q, off, out);
}

// round 5
// speedup vs baseline: 10.0463x; 1.9172x over previous
#include <cuda_runtime.h>
#include <cuda_bf16.h>
#include <cstdint>

// Problem shape (fixed)
#define B   64
#define C   64
#define NQ  32
#define S   1024
#define KD  128          // embedding dim
#define MT  128          // rows per block (4 b's * 32 n)
#define NT  128          // doc tokens per s-tile
#define PADB 136         // smem row stride in bf16 elems
#define TEMP_INV 50.0f

__device__ float g_scores[B * C];
__device__ __nv_bfloat16 g_qbf[B * NQ * KD];   // 0.5 MB
__device__ __nv_bfloat16 g_dbf[C * S * KD];    // 16 MB

__device__ __forceinline__ uint32_t s2u(const void* p) {
    return (uint32_t)__cvta_generic_to_shared(p);
}
__device__ __forceinline__ void cp_async16(void* dst, const void* src) {
    asm volatile("cp.async.cg.shared.global [%0], [%1], 16;\n"
                 :: "r"(s2u(dst)), "l"(src));
}
__device__ __forceinline__ uint32_t pack_bf16x2(float lo, float hi) {
    __nv_bfloat162 h = __floats2bfloat162_rn(lo, hi);
    return *reinterpret_cast<uint32_t*>(&h);
}

// ---------------------------------------------------------------------------
// Kernel 0: fp32 -> bf16 conversion of q and d (one-time, ~8 us)
// ---------------------------------------------------------------------------
__global__ void convert_bf16_kernel(const float* __restrict__ q,
                                    const float* __restrict__ d)
{
    const size_t nq4 = (size_t)B * NQ * KD / 4;        // 65536
    const size_t nd4 = (size_t)C * S  * KD / 4;        // 2097152
    const size_t stride = (size_t)gridDim.x * blockDim.x;
    for (size_t idx = (size_t)blockIdx.x * blockDim.x + threadIdx.x;
         idx < nq4 + nd4; idx += stride) {
        float4 v;
        if (idx < nq4) v = reinterpret_cast<const float4*>(q)[idx];
        else           v = reinterpret_cast<const float4*>(d)[idx - nq4];
        uint2 o;
        o.x = pack_bf16x2(v.x, v.y);
        o.y = pack_bf16x2(v.z, v.w);
        if (idx < nq4) reinterpret_cast<uint2*>(g_qbf)[idx]       = o;
        else           reinterpret_cast<uint2*>(g_dbf)[idx - nq4] = o;
    }
}

// ---------------------------------------------------------------------------
// Kernel 1: bf16 mma.sync m16n8k16 GEMM with fused max/sum epilogue.
// Block (mtile, c): 128 Q-rows x all 1024 doc tokens of c, 8 s-tiles.
// 8 warps: 4(M) x 2(N); warp tile 32x64. Double-buffered cp.async on D.
// 2 CTAs/SM (smem ~102 KB each).
// ---------------------------------------------------------------------------
__global__ __launch_bounds__(256, 2)
void colbert_scores_mma(void)
{
    extern __shared__ __nv_bfloat16 shb[];
    __nv_bfloat16* qs = shb;                    // MT * PADB
    __nv_bfloat16* ds = shb + MT * PADB;        // 2 * NT * PADB (double buffer)

    const int mtile = blockIdx.x;      // 0..15
    const int c     = blockIdx.y;      // 0..63
    const int tid   = threadIdx.x;
    const int wid   = tid >> 5;
    const int lane  = tid & 31;
    const int warp_m = wid >> 1;       // 0..3
    const int warp_n = wid & 1;        // 0..1
    const int gID   = lane >> 2;
    const int tig   = lane & 3;

    const __nv_bfloat16* __restrict__ qbase = g_qbf + (size_t)mtile * MT * KD;
    const __nv_bfloat16* __restrict__ dbase = g_dbf + (size_t)c * S * KD;

    // ---- load Q tile (once): 128x128 bf16 = 32 KB = 2048 x 16B chunks ----
    #pragma unroll
    for (int i = 0; i < 8; i++) {               // full tile: 8*256 = 2048 chunks
        int idx = i * 256 + tid;                // chunk index 0..2047
        int row = idx >> 4;                     // 16 chunks per row
        int c8  = idx & 15;
        cp_async16(&qs[row * PADB + c8 * 8], qbase + (size_t)row * KD + c8 * 8);
    }
    // ---- prefetch D s-tile 0: also 2048 chunks ----
    #pragma unroll
    for (int i = 0; i < 8; i++) {
        int idx = i * 256 + tid;
        int row = idx >> 4;
        int c8  = idx & 15;
        cp_async16(&ds[row * PADB + c8 * 8], dbase + (size_t)row * KD + c8 * 8);
    }
    asm volatile("cp.async.commit_group;\n");

    float runmax[2][2];
    #pragma unroll
    for (int mt = 0; mt < 2; mt++)
        #pragma unroll
        for (int h = 0; h < 2; h++)
            runmax[mt][h] = __int_as_float(0xff800000);

    for (int t = 0; t < S / NT; t++) {
        if (t < S / NT - 1) {
            __nv_bfloat16* dst = ds + ((t + 1) & 1) * NT * PADB;
            const __nv_bfloat16* src = dbase + (size_t)(t + 1) * NT * KD;
            #pragma unroll
            for (int i = 0; i < 8; i++) {
                int idx = i * 256 + tid;
                int row = idx >> 4;
                int c8  = idx & 15;
                cp_async16(&dst[row * PADB + c8 * 8], src + (size_t)row * KD + c8 * 8);
            }
            asm volatile("cp.async.commit_group;\n");
            asm volatile("cp.async.wait_group 1;\n");
        } else {
            asm volatile("cp.async.wait_group 0;\n");
        }
        __syncthreads();   // tile t (and Q on t=0) visible to all warps

        const __nv_bfloat16* db = ds + (t & 1) * NT * PADB;

        float acc[2][8][4];
        #pragma unroll
        for (int mt = 0; mt < 2; mt++)
            #pragma unroll
            for (int nt = 0; nt < 8; nt++)
                #pragma unroll
                for (int r = 0; r < 4; r++) acc[mt][nt][r] = 0.0f;

        const int arow = warp_m * 32 + gID;
        const int brow = warp_n * 64 + gID;

        #pragma unroll
        for (int ks = 0; ks < 8; ks++) {
            const int k0 = ks * 16;
            // A fragments: m16n8k16 row-major
            uint32_t a[2][4];
            #pragma unroll
            for (int mt = 0; mt < 2; mt++) {
                const __nv_bfloat16* ap =
                    &qs[(arow + mt * 16) * PADB + k0 + 2 * tig];
                a[mt][0] = *reinterpret_cast<const uint32_t*>(ap);
                a[mt][1] = *reinterpret_cast<const uint32_t*>(ap + 8 * PADB);
                a[mt][2] = *reinterpret_cast<const uint32_t*>(ap + 8);
                a[mt][3] = *reinterpret_cast<const uint32_t*>(ap + 8 * PADB + 8);
            }
            uint32_t bf[8][2];
            #pragma unroll
            for (int nt = 0; nt < 8; nt++) {
                const __nv_bfloat16* bp =
                    &db[(brow + nt * 8) * PADB + k0 + 2 * tig];
                bf[nt][0] = *reinterpret_cast<const uint32_t*>(bp);
                bf[nt][1] = *reinterpret_cast<const uint32_t*>(bp + 8);
            }
            #pragma unroll
            for (int mt = 0; mt < 2; mt++)
                #pragma unroll
                for (int nt = 0; nt < 8; nt++) {
                    asm volatile(
                        "mma.sync.aligned.m16n8k16.row.col.f32.bf16.bf16.f32 "
                        "{%0,%1,%2,%3}, {%4,%5,%6,%7}, {%8,%9}, {%0,%1,%2,%3};\n"
                        : "+f"(acc[mt][nt][0]), "+f"(acc[mt][nt][1]),
                          "+f"(acc[mt][nt][2]), "+f"(acc[mt][nt][3])
                        : "r"(a[mt][0]), "r"(a[mt][1]), "r"(a[mt][2]), "r"(a[mt][3]),
                          "r"(bf[nt][0]), "r"(bf[nt][1]));
                }
        }

        // c0,c1 -> row gID; c2,c3 -> row gID+8. Cols irrelevant (max over s).
        #pragma unroll
        for (int mt = 0; mt < 2; mt++) {
            float m0 = __int_as_float(0xff800000);
            float m1 = __int_as_float(0xff800000);
            #pragma unroll
            for (int nt = 0; nt < 8; nt++) {
                m0 = fmaxf(m0, fmaxf(acc[mt][nt][0], acc[mt][nt][1]));
                m1 = fmaxf(m1, fmaxf(acc[mt][nt][2], acc[mt][nt][3]));
            }
            runmax[mt][0] = fmaxf(runmax[mt][0], m0);
            runmax[mt][1] = fmaxf(runmax[mt][1], m1);
        }
        __syncthreads();   // buffer reads done before next prefetch overwrites
    }

    // ---- reduce: quad max across tig, publish per (warp_n, row) ----
    float* red = reinterpret_cast<float*>(shb);   // reuse smem: 2*128 floats
    #pragma unroll
    for (int mt = 0; mt < 2; mt++)
        #pragma unroll
        for (int h = 0; h < 2; h++) {
            float m = runmax[mt][h];
            m = fmaxf(m, __shfl_xor_sync(0xffffffffu, m, 1));
            m = fmaxf(m, __shfl_xor_sync(0xffffffffu, m, 2));
            if (tig == 0) {
                int row = warp_m * 32 + mt * 16 + h * 8 + gID;
                red[warp_n * 128 + row] = m;
            }
        }
    __syncthreads();

    // rows wid*32..+31 belong to b_global = mtile*4 + wid; n = lane
    if (wid < 4) {
        int row = wid * 32 + lane;
        float v = fmaxf(red[row], red[128 + row]);
        #pragma unroll
        for (int off = 16; off > 0; off >>= 1)
            v += __shfl_xor_sync(0xffffffffu, v, off);
        if (lane == 0)
            g_scores[(mtile * 4 + wid) * C + c] = v;
    }
}

// ---------------------------------------------------------------------------
// Kernel 2: normalize, log-softmax, NLL mean. Warp-parallel: 16 warps x 4 rows.
// ---------------------------------------------------------------------------
__global__ void colbert_loss_kernel(const float* __restrict__ q,
                                    const int*   __restrict__ offset_p,
                                    float*       __restrict__ out)
{
    __shared__ float losses[B];
    const int tid  = threadIdx.x;
    const int wid  = tid >> 5;
    const int lane = tid & 31;
    const int label_off = offset_p[0];

    #pragma unroll
    for (int r = 0; r < 4; r++) {
        const int b = wid * 4 + r;
        // length: count of q[b, n, 0] != 0 over n = lane (NQ == 32)
        unsigned bal = __ballot_sync(0xffffffffu,
                          q[(size_t)b * NQ * KD + (size_t)lane * KD] != 0.0f);
        const float inv = TEMP_INV / (float)__popc(bal);

        float l0 = g_scores[b * C + lane]      * inv;
        float l1 = g_scores[b * C + 32 + lane] * inv;

        float mx = fmaxf(l0, l1);
        #pragma unroll
        for (int o = 16; o > 0; o >>= 1)
            mx = fmaxf(mx, __shfl_xor_sync(0xffffffffu, mx, o));

        float se = expf(l0 - mx) + expf(l1 - mx);
        #pragma unroll
        for (int o = 16; o > 0; o >>= 1)
            se += __shfl_xor_sync(0xffffffffu, se, o);

        const int label = b + label_off;
        const float ll = (label < 32)
                       ? __shfl_sync(0xffffffffu, l0, label)
                       : __shfl_sync(0xffffffffu, l1, label - 32);
        if (lane == 0)
            losses[b] = -(ll - mx - logf(se));
    }
    __syncthreads();

    if (tid < 32) {
        float v = losses[tid] + losses[tid + 32];
        #pragma unroll
        for (int o = 16; o > 0; o >>= 1)
            v += __shfl_xor_sync(0xffffffffu, v, o);
        if (tid == 0) out[0] = v / (float)B;
    }
}

// ---------------------------------------------------------------------------
extern "C" void kernel_launch(void* const* d_in, const int* in_sizes, int n_in,
                              void* d_out, int out_size)
{
    const float* q   = (const float*)d_in[0];
    const float* d   = (const float*)d_in[1];
    const int*   off = (const int*)  d_in[2];
    float*       out = (float*)d_out;

    const size_t smem_bytes = (size_t)(MT * PADB + 2 * NT * PADB)
                              * sizeof(__nv_bfloat16);   // 104448

    cudaFuncSetAttribute(colbert_scores_mma,
                         cudaFuncAttributeMaxDynamicSharedMemorySize,
                         (int)smem_bytes);

    convert_bf16_kernel<<<1024, 256>>>(q, d);
    dim3 grid(16, C);
    colbert_scores_mma<<<grid, 256, smem_bytes>>>();
    colbert_loss_kernel<<<1, 512>>>(q, off, out);
}

// round 7
// speedup vs baseline: 10.5078x; 1.0459x over previous
#include <cuda_runtime.h>
#include <cuda_bf16.h>
#include <cstdint>

// Problem shape (fixed)
#define B   64
#define C   64
#define NQ  32
#define S   1024
#define KD  128          // embedding dim
#define MT  128          // rows per block (4 b's * 32 n)
#define NT  128          // doc tokens per s-tile
#define PADB 136         // smem row stride in bf16 elems
#define TEMP_INV 50.0f

__device__ float g_scores[B * C];
__device__ __nv_bfloat16 g_qbf[B * NQ * KD];   // 0.5 MB
__device__ __nv_bfloat16 g_dbf[C * S * KD];    // 16 MB

__device__ __forceinline__ uint32_t s2u(const void* p) {
    return (uint32_t)__cvta_generic_to_shared(p);
}
__device__ __forceinline__ void cp_async16(void* dst, const void* src) {
    asm volatile("cp.async.cg.shared.global [%0], [%1], 16;\n"
                 :: "r"(s2u(dst)), "l"(src));
}
__device__ __forceinline__ uint32_t pack_bf16x2(float lo, float hi) {
    __nv_bfloat162 h = __floats2bfloat162_rn(lo, hi);
    return *reinterpret_cast<uint32_t*>(&h);
}

// ---------------------------------------------------------------------------
// Kernel 0: fp32 -> bf16 conversion of q and d (one-time, ~10 us, DRAM-bound)
// ---------------------------------------------------------------------------
__global__ void convert_bf16_kernel(const float* __restrict__ q,
                                    const float* __restrict__ d)
{
    const size_t nq4 = (size_t)B * NQ * KD / 4;        // 65536
    const size_t nd4 = (size_t)C * S  * KD / 4;        // 2097152
    const size_t stride = (size_t)gridDim.x * blockDim.x;
    for (size_t idx = (size_t)blockIdx.x * blockDim.x + threadIdx.x;
         idx < nq4 + nd4; idx += stride) {
        float4 v;
        if (idx < nq4) v = reinterpret_cast<const float4*>(q)[idx];
        else           v = reinterpret_cast<const float4*>(d)[idx - nq4];
        uint2 o;
        o.x = pack_bf16x2(v.x, v.y);
        o.y = pack_bf16x2(v.z, v.w);
        if (idx < nq4) reinterpret_cast<uint2*>(g_qbf)[idx]       = o;
        else           reinterpret_cast<uint2*>(g_dbf)[idx - nq4] = o;
    }
}

// ---------------------------------------------------------------------------
// Kernel 1: bf16 mma.sync m16n8k16 GEMM, fused max/sum epilogue.
// 4 warps (128 thr), warp grid 2x2, warp tile 64x64 (4 m-frags x 8 n-frags).
// Fragment smem traffic per 128x128 tile: 32K*2 + 32K*2 = 128 KB
// (vs 192 KB with the old 4x2 grid) -> crossbar floor 1024 cyc/tile.
// 2 CTAs/SM (smem 102 KB, regs ~200).
// ---------------------------------------------------------------------------
__global__ __launch_bounds__(128, 2)
void colbert_scores_mma(void)
{
    extern __shared__ __nv_bfloat16 shb[];
    __nv_bfloat16* qs = shb;                    // MT * PADB
    __nv_bfloat16* ds = shb + MT * PADB;        // 2 * NT * PADB (double buffer)

    const int mtile = blockIdx.x;      // 0..15
    const int c     = blockIdx.y;      // 0..63
    const int tid   = threadIdx.x;
    const int wid   = tid >> 5;        // 0..3
    const int lane  = tid & 31;
    const int warp_m = wid >> 1;       // 0..1
    const int warp_n = wid & 1;        // 0..1
    const int gID   = lane >> 2;
    const int tig   = lane & 3;

    const __nv_bfloat16* __restrict__ qbase = g_qbf + (size_t)mtile * MT * KD;
    const __nv_bfloat16* __restrict__ dbase = g_dbf + (size_t)c * S * KD;

    // ---- load Q tile (once): 2048 x 16B chunks, 16 per thread ----
    #pragma unroll
    for (int i = 0; i < 16; i++) {
        int idx = i * 128 + tid;
        int row = idx >> 4;
        int c8  = idx & 15;
        cp_async16(&qs[row * PADB + c8 * 8], qbase + (size_t)row * KD + c8 * 8);
    }
    // ---- prefetch D s-tile 0 ----
    #pragma unroll
    for (int i = 0; i < 16; i++) {
        int idx = i * 128 + tid;
        int row = idx >> 4;
        int c8  = idx & 15;
        cp_async16(&ds[row * PADB + c8 * 8], dbase + (size_t)row * KD + c8 * 8);
    }
    asm volatile("cp.async.commit_group;\n");

    float runmax[4][2];
    #pragma unroll
    for (int mt = 0; mt < 4; mt++)
        #pragma unroll
        for (int h = 0; h < 2; h++)
            runmax[mt][h] = __int_as_float(0xff800000);

    for (int t = 0; t < S / NT; t++) {
        if (t < S / NT - 1) {
            __nv_bfloat16* dst = ds + ((t + 1) & 1) * NT * PADB;
            const __nv_bfloat16* src = dbase + (size_t)(t + 1) * NT * KD;
            #pragma unroll
            for (int i = 0; i < 16; i++) {
                int idx = i * 128 + tid;
                int row = idx >> 4;
                int c8  = idx & 15;
                cp_async16(&dst[row * PADB + c8 * 8], src + (size_t)row * KD + c8 * 8);
            }
            asm volatile("cp.async.commit_group;\n");
            asm volatile("cp.async.wait_group 1;\n");
        } else {
            asm volatile("cp.async.wait_group 0;\n");
        }
        __syncthreads();   // tile t (and Q on t=0) visible to all warps

        const __nv_bfloat16* db = ds + (t & 1) * NT * PADB;

        float acc[4][8][4];
        #pragma unroll
        for (int mt = 0; mt < 4; mt++)
            #pragma unroll
            for (int nt = 0; nt < 8; nt++)
                #pragma unroll
                for (int r = 0; r < 4; r++) acc[mt][nt][r] = 0.0f;

        const int arow = warp_m * 64 + gID;
        const int brow = warp_n * 64 + gID;

        #pragma unroll
        for (int ks = 0; ks < 8; ks++) {
            const int k0 = ks * 16;
            uint32_t a[4][4];
            #pragma unroll
            for (int mt = 0; mt < 4; mt++) {
                const __nv_bfloat16* ap =
                    &qs[(arow + mt * 16) * PADB + k0 + 2 * tig];
                a[mt][0] = *reinterpret_cast<const uint32_t*>(ap);
                a[mt][1] = *reinterpret_cast<const uint32_t*>(ap + 8 * PADB);
                a[mt][2] = *reinterpret_cast<const uint32_t*>(ap + 8);
                a[mt][3] = *reinterpret_cast<const uint32_t*>(ap + 8 * PADB + 8);
            }
            uint32_t bf[8][2];
            #pragma unroll
            for (int nt = 0; nt < 8; nt++) {
                const __nv_bfloat16* bp =
                    &db[(brow + nt * 8) * PADB + k0 + 2 * tig];
                bf[nt][0] = *reinterpret_cast<const uint32_t*>(bp);
                bf[nt][1] = *reinterpret_cast<const uint32_t*>(bp + 8);
            }
            #pragma unroll
            for (int mt = 0; mt < 4; mt++)
                #pragma unroll
                for (int nt = 0; nt < 8; nt++) {
                    asm volatile(
                        "mma.sync.aligned.m16n8k16.row.col.f32.bf16.bf16.f32 "
                        "{%0,%1,%2,%3}, {%4,%5,%6,%7}, {%8,%9}, {%0,%1,%2,%3};\n"
                        : "+f"(acc[mt][nt][0]), "+f"(acc[mt][nt][1]),
                          "+f"(acc[mt][nt][2]), "+f"(acc[mt][nt][3])
                        : "r"(a[mt][0]), "r"(a[mt][1]), "r"(a[mt][2]), "r"(a[mt][3]),
                          "r"(bf[nt][0]), "r"(bf[nt][1]));
                }
        }

        // c0,c1 -> row gID; c2,c3 -> row gID+8. Cols irrelevant (max over s).
        #pragma unroll
        for (int mt = 0; mt < 4; mt++) {
            float m0 = __int_as_float(0xff800000);
            float m1 = __int_as_float(0xff800000);
            #pragma unroll
            for (int nt = 0; nt < 8; nt++) {
                m0 = fmaxf(m0, fmaxf(acc[mt][nt][0], acc[mt][nt][1]));
                m1 = fmaxf(m1, fmaxf(acc[mt][nt][2], acc[mt][nt][3]));
            }
            runmax[mt][0] = fmaxf(runmax[mt][0], m0);
            runmax[mt][1] = fmaxf(runmax[mt][1], m1);
        }
        __syncthreads();   // buffer reads done before next prefetch overwrites
    }

    // ---- reduce: quad max across tig, publish per (warp_n, row) ----
    float* red = reinterpret_cast<float*>(shb);   // reuse smem: 2*128 floats
    #pragma unroll
    for (int mt = 0; mt < 4; mt++)
        #pragma unroll
        for (int h = 0; h < 2; h++) {
            float m = runmax[mt][h];
            m = fmaxf(m, __shfl_xor_sync(0xffffffffu, m, 1));
            m = fmaxf(m, __shfl_xor_sync(0xffffffffu, m, 2));
            if (tig == 0) {
                int row = warp_m * 64 + mt * 16 + h * 8 + gID;
                red[warp_n * 128 + row] = m;
            }
        }
    __syncthreads();

    // rows wid*32..+31 belong to b_global = mtile*4 + wid; n = lane
    {
        int row = wid * 32 + lane;
        float v = fmaxf(red[row], red[128 + row]);
        #pragma unroll
        for (int off = 16; off > 0; off >>= 1)
            v += __shfl_xor_sync(0xffffffffu, v, off);
        if (lane == 0)
            g_scores[(mtile * 4 + wid) * C + c] = v;
    }
}

// ---------------------------------------------------------------------------
// Kernel 2: normalize, log-softmax, NLL mean. Warp-parallel: 16 warps x 4 rows.
// ---------------------------------------------------------------------------
__global__ void colbert_loss_kernel(const float* __restrict__ q,
                                    const int*   __restrict__ offset_p,
                                    float*       __restrict__ out)
{
    __shared__ float losses[B];
    const int tid  = threadIdx.x;
    const int wid  = tid >> 5;
    const int lane = tid & 31;
    const int label_off = offset_p[0];

    #pragma unroll
    for (int r = 0; r < 4; r++) {
        const int b = wid * 4 + r;
        // length: count of q[b, n, 0] != 0 over n = lane (NQ == 32)
        unsigned bal = __ballot_sync(0xffffffffu,
                          q[(size_t)b * NQ * KD + (size_t)lane * KD] != 0.0f);
        const float inv = TEMP_INV / (float)__popc(bal);

        float l0 = g_scores[b * C + lane]      * inv;
        float l1 = g_scores[b * C + 32 + lane] * inv;

        float mx = fmaxf(l0, l1);
        #pragma unroll
        for (int o = 16; o > 0; o >>= 1)
            mx = fmaxf(mx, __shfl_xor_sync(0xffffffffu, mx, o));

        float se = expf(l0 - mx) + expf(l1 - mx);
        #pragma unroll
        for (int o = 16; o > 0; o >>= 1)
            se += __shfl_xor_sync(0xffffffffu, se, o);

        const int label = b + label_off;
        const float ll = (label < 32)
                       ? __shfl_sync(0xffffffffu, l0, label)
                       : __shfl_sync(0xffffffffu, l1, label - 32);
        if (lane == 0)
            losses[b] = -(ll - mx - logf(se));
    }
    __syncthreads();

    if (tid < 32) {
        float v = losses[tid] + losses[tid + 32];
        #pragma unroll
        for (int o = 16; o > 0; o >>= 1)
            v += __shfl_xor_sync(0xffffffffu, v, o);
        if (tid == 0) out[0] = v / (float)B;
    }
}

// ---------------------------------------------------------------------------
extern "C" void kernel_launch(void* const* d_in, const int* in_sizes, int n_in,
                              void* d_out, int out_size)
{
    const float* q   = (const float*)d_in[0];
    const float* d   = (const float*)d_in[1];
    const int*   off = (const int*)  d_in[2];
    float*       out = (float*)d_out;

    const size_t smem_bytes = (size_t)(MT * PADB + 2 * NT * PADB)
                              * sizeof(__nv_bfloat16);   // 104448

    cudaFuncSetAttribute(colbert_scores_mma,
                         cudaFuncAttributeMaxDynamicSharedMemorySize,
                         (int)smem_bytes);

    convert_bf16_kernel<<<1024, 256>>>(q, d);
    dim3 grid(16, C);
    colbert_scores_mma<<<grid, 128, smem_bytes>>>();
    colbert_loss_kernel<<<1, 512>>>(q, off, out);
}